// round 2
// baseline (speedup 1.0000x reference)
#include <cuda_runtime.h>
#include <cuda_bf16.h>

// Problem shape: mlm_outputs [256, 4096, 30] f32, nsp_outputs [256,2] f32,
// mutation_matrix [30,30] f32 (mathematically cancels), mlm_targets [256*4096] i32,
// is_nexts [256] i32 (unused).
// Output (fp32): [mlm_predictions (B*S) | nsp_predictions (B) | loss (1)]

#define VOCAB 30
#define ROWS_PER_BLOCK 256
#define THREADS 256
#define TILE_FLOATS (ROWS_PER_BLOCK * VOCAB)   // 7680 floats = 30720 B
#define FIXED_SCALE 4294967296.0               // 2^32 Q32.32 fixed point

__device__ unsigned long long g_acc;

__global__ void init_kernel() { g_acc = 0ull; }

__global__ void __launch_bounds__(THREADS)
mlm_kernel(const float* __restrict__ mlm,
           const int*   __restrict__ tgt,
           float*       __restrict__ out)
{
    __shared__ float s[TILE_FLOATS];
    __shared__ unsigned long long warp_sums[THREADS / 32];

    const int tid = threadIdx.x;

    // ---- Stage tile (256 rows x 30 floats) with fully coalesced float4 loads ----
    const size_t tile_base = (size_t)blockIdx.x * TILE_FLOATS;
    const float4* g4 = reinterpret_cast<const float4*>(mlm + tile_base);
    float4* s4 = reinterpret_cast<float4*>(s);
    #pragma unroll
    for (int i = 0; i < 8; ++i) {
        int idx = tid + i * THREADS;
        if (idx < TILE_FLOATS / 4) s4[idx] = g4[idx];
    }
    __syncthreads();

    // ---- One row per thread, single pass from smem into registers ----
    const int row = blockIdx.x * ROWS_PER_BLOCK + tid;
    const int t   = tgt[row];

    float x[VOCAB];
    #pragma unroll
    for (int i = 0; i < VOCAB; ++i) x[i] = s[tid * VOCAB + i];

    // argmax (strict > keeps first max index, matching jnp.argmax)
    float mx = x[0];
    int   am = 0;
    #pragma unroll
    for (int i = 1; i < VOCAB; ++i)
        if (x[i] > mx) { mx = x[i]; am = i; }

    // logsumexp + pick x[target] via predicated select (keeps x[] in registers)
    float xt  = x[0];
    float sum = 0.0f;
    #pragma unroll
    for (int i = 0; i < VOCAB; ++i) {
        sum += __expf(x[i] - mx);
        if (i == t) xt = x[i];
    }
    float nll = __logf(sum) + mx - xt;   // logsumexp(x) - x[t]  >= 0

    out[row] = (float)am;

    // ---- Deterministic masked accumulation: Q32.32 fixed point ----
    float contrib = (t != 0) ? nll : 0.0f;
    unsigned long long ll =
        (unsigned long long)__double2ll_rn((double)contrib * FIXED_SCALE);

    #pragma unroll
    for (int o = 16; o > 0; o >>= 1)
        ll += __shfl_down_sync(0xffffffffu, ll, o);
    if ((tid & 31) == 0) warp_sums[tid >> 5] = ll;
    __syncthreads();

    if (tid == 0) {
        unsigned long long total = 0ull;
        #pragma unroll
        for (int w = 0; w < THREADS / 32; ++w) total += warp_sums[w];
        atomicAdd(&g_acc, total);   // 4096 atomics total, integer => exact
    }
}

__global__ void finalize_kernel(const float* __restrict__ nsp,
                                float* __restrict__ out,
                                int n_rows, int B, int out_size)
{
    int b = threadIdx.x;
    if (b < B) {
        float v0 = nsp[2 * b];
        float v1 = nsp[2 * b + 1];
        // first-max tie-break: index 1 only if strictly greater
        out[n_rows + b] = (v1 > v0) ? 1.0f : 0.0f;
    }
    if (b == 0) {
        double s = (double)g_acc / FIXED_SCALE;
        out[out_size - 1] = (float)(s / (double)n_rows);
    }
}

extern "C" void kernel_launch(void* const* d_in, const int* in_sizes, int n_in,
                              void* d_out, int out_size)
{
    const float* mlm = (const float*)d_in[0];   // [B*S*V] f32
    const float* nsp = (const float*)d_in[1];   // [B*2]   f32
    // d_in[2] = mutation_matrix (unused: weight cancels exactly)
    const int*   tgt = (const int*)d_in[3];     // [B*S]   i32
    // d_in[4] = is_nexts (unused)

    const int n_rows = in_sizes[3];             // B*S = 1048576
    const int B      = in_sizes[4];             // 256
    float* out = (float*)d_out;

    init_kernel<<<1, 1>>>();
    mlm_kernel<<<n_rows / ROWS_PER_BLOCK, THREADS>>>(mlm, tgt, out);
    finalize_kernel<<<1, THREADS>>>(nsp, out, n_rows, B, out_size);
}